// round 6
// baseline (speedup 1.0000x reference)
#include <cuda_runtime.h>
#include <math.h>

#define S_LEN 4096
#define D_MODEL 1024
#define NH 16
#define DHD 64

// ---- scratch (static device globals: allocation-free contract) ----
__device__ float g_h[S_LEN * D_MODEL];
__device__ float g_q[S_LEN * D_MODEL];
__device__ float g_k[S_LEN * D_MODEL];
__device__ float g_v[S_LEN * D_MODEL];
__device__ float g_att[S_LEN * D_MODEL];
__device__ float g_proj[S_LEN * D_MODEL];

// ---------------------------------------------------------------------------
// h = x + positional_encoding
// ---------------------------------------------------------------------------
__global__ void add_pe_kernel(const float* __restrict__ x, float* __restrict__ h) {
    int srow = blockIdx.x;
    int tid = threadIdx.x;
#pragma unroll
    for (int n = 0; n < 4; n++) {
        int d = tid + n * 256;
        float arg = (float)(d & ~1) * (-9.2103403719761836f / 1024.0f);  // -ln(10000)/D
        float dv = expf(arg);
        float a = (float)srow * dv;
        float pe = (d & 1) ? cosf(a) : sinf(a);
        int idx = srow * D_MODEL + d;
        h[idx] = x[idx] + pe;
    }
}

// ---------------------------------------------------------------------------
// tf32 helpers
// ---------------------------------------------------------------------------
__device__ __forceinline__ unsigned f2tf32(float x) {
    unsigned r;
    asm("cvt.rna.tf32.f32 %0, %1;" : "=r"(r) : "f"(x));
    return r;
}

__device__ __forceinline__ void mma_tf32(
    float& c0, float& c1, float& c2, float& c3,
    unsigned a0, unsigned a1, unsigned a2, unsigned a3,
    unsigned b0, unsigned b1) {
    asm("mma.sync.aligned.m16n8k8.row.col.f32.tf32.tf32.f32 "
        "{%0,%1,%2,%3}, {%4,%5,%6,%7}, {%8,%9}, {%0,%1,%2,%3};"
        : "+f"(c0), "+f"(c1), "+f"(c2), "+f"(c3)
        : "r"(a0), "r"(a1), "r"(a2), "r"(a3), "r"(b0), "r"(b1));
}

// ---------------------------------------------------------------------------
// 128x128x16 tf32 tensor-core GEMM body, double-buffered, fp32 accumulate.
// C = A@B + bias. 8 warps: warp_m = wid&3 (32 rows), warp_n = wid>>2 (64 cols).
// Per warp: 2 m-tiles (m16) x 8 n-tiles (n8). Smem is [k][m]/[k][n] with
// pitch 136 (mod 32 = 8) so fragment LDS banks (8*tig + gid) are distinct.
// ---------------------------------------------------------------------------
#define KT 16
#define PITCH 136

__device__ __forceinline__ void sgemm_body(
    const float* __restrict__ A, const float* __restrict__ B,
    const float* __restrict__ bias, float* __restrict__ C,
    int M, int N, int K, int m0, int n0) {
    __shared__ unsigned As[2][KT][PITCH];
    __shared__ unsigned Bs[2][KT][PITCH];

    int tid = threadIdx.x;
    int wid = tid >> 5;
    int lane = tid & 31;
    int gid = lane >> 2;       // 0..7
    int tig = lane & 3;        // 0..3
    int wm = (wid & 3) * 32;   // warp row offset in tile
    int wn = (wid >> 2) * 64;  // warp col offset in tile

    // gmem load mapping
    int arow = tid >> 1;          // 0..127
    int acol = (tid & 1) * 4;     // 0 or 4 (second fragment at +8)
    int brow = tid >> 5;          // 0..7   (second fragment at +8)
    int bcol = (tid & 31) * 4;    // 0..124

    const float* Aptr = &A[(size_t)(m0 + arow) * K + acol];
    const float* Bptr = &B[(size_t)brow * N + n0 + bcol];

    float acc[2][8][4];
#pragma unroll
    for (int mt = 0; mt < 2; mt++)
#pragma unroll
        for (int nt = 0; nt < 8; nt++)
#pragma unroll
            for (int r = 0; r < 4; r++) acc[mt][nt][r] = 0.f;

    // prologue: tile 0 -> buffer 0
    float4 a0p = *(const float4*)Aptr;
    float4 a1p = *(const float4*)(Aptr + 8);
    float4 b0p = *(const float4*)Bptr;
    float4 b1p = *(const float4*)(Bptr + (size_t)8 * N);
#pragma unroll
    for (int i = 0; i < 4; i++) {
        As[0][acol + i][arow]     = f2tf32(((const float*)&a0p)[i]);
        As[0][acol + 8 + i][arow] = f2tf32(((const float*)&a1p)[i]);
        Bs[0][brow][bcol + i]     = f2tf32(((const float*)&b0p)[i]);
        Bs[0][brow + 8][bcol + i] = f2tf32(((const float*)&b1p)[i]);
    }
    __syncthreads();

    int buf = 0;
    for (int k0 = 0; k0 < K; k0 += KT) {
        // issue next tile's gmem loads early
        if (k0 + KT < K) {
            a0p = *(const float4*)(Aptr + k0 + KT);
            a1p = *(const float4*)(Aptr + k0 + KT + 8);
            b0p = *(const float4*)(Bptr + (size_t)(k0 + KT) * N);
            b1p = *(const float4*)(Bptr + (size_t)(k0 + KT + 8) * N);
        }

#pragma unroll
        for (int ks = 0; ks < KT; ks += 8) {
            unsigned af[2][4], bf[8][2];
#pragma unroll
            for (int mt = 0; mt < 2; mt++) {
                int r = wm + mt * 16 + gid;
                af[mt][0] = As[buf][ks + tig][r];
                af[mt][1] = As[buf][ks + tig][r + 8];
                af[mt][2] = As[buf][ks + tig + 4][r];
                af[mt][3] = As[buf][ks + tig + 4][r + 8];
            }
#pragma unroll
            for (int nt = 0; nt < 8; nt++) {
                int c = wn + nt * 8 + gid;
                bf[nt][0] = Bs[buf][ks + tig][c];
                bf[nt][1] = Bs[buf][ks + tig + 4][c];
            }
#pragma unroll
            for (int mt = 0; mt < 2; mt++)
#pragma unroll
                for (int nt = 0; nt < 8; nt++)
                    mma_tf32(acc[mt][nt][0], acc[mt][nt][1],
                             acc[mt][nt][2], acc[mt][nt][3],
                             af[mt][0], af[mt][1], af[mt][2], af[mt][3],
                             bf[nt][0], bf[nt][1]);
        }

        if (k0 + KT < K) {
            int nb = buf ^ 1;
#pragma unroll
            for (int i = 0; i < 4; i++) {
                As[nb][acol + i][arow]     = f2tf32(((const float*)&a0p)[i]);
                As[nb][acol + 8 + i][arow] = f2tf32(((const float*)&a1p)[i]);
                Bs[nb][brow][bcol + i]     = f2tf32(((const float*)&b0p)[i]);
                Bs[nb][brow + 8][bcol + i] = f2tf32(((const float*)&b1p)[i]);
            }
            __syncthreads();
            buf = nb;
        }
    }

    // epilogue: c0,c1 -> (row, 2tig); c2,c3 -> (row+8, 2tig)
#pragma unroll
    for (int mt = 0; mt < 2; mt++) {
#pragma unroll
        for (int nt = 0; nt < 8; nt++) {
            int row = m0 + wm + mt * 16 + gid;
            int col = n0 + wn + nt * 8 + tig * 2;
            float2 r0, r1;
            r0.x = acc[mt][nt][0] + bias[col];
            r0.y = acc[mt][nt][1] + bias[col + 1];
            r1.x = acc[mt][nt][2] + bias[col];
            r1.y = acc[mt][nt][3] + bias[col + 1];
            *(float2*)&C[(size_t)row * N + col]       = r0;
            *(float2*)&C[(size_t)(row + 8) * N + col] = r1;
        }
    }
}

// Plain single-output GEMM (out projection)
__global__ __launch_bounds__(256) void sgemm_bias_kernel(
    const float* __restrict__ A, const float* __restrict__ B,
    const float* __restrict__ bias, float* __restrict__ C,
    int M, int N, int K) {
    sgemm_body(A, B, bias, C, M, N, K, blockIdx.y * 128, blockIdx.x * 128);
}

// Fused QKV: blockIdx.z in {0,1,2} selects (Wq,bq,q)/(Wk,bk,k)/(Wv,bv,v).
__global__ __launch_bounds__(256) void sgemm_qkv_kernel(
    const float* __restrict__ A,
    const float* __restrict__ Wq, const float* __restrict__ bq, float* __restrict__ q,
    const float* __restrict__ Wk, const float* __restrict__ bk, float* __restrict__ k,
    const float* __restrict__ Wv, const float* __restrict__ bv, float* __restrict__ v) {
    const float* B;
    const float* bias;
    float* C;
    if (blockIdx.z == 0)      { B = Wq; bias = bq; C = q; }
    else if (blockIdx.z == 1) { B = Wk; bias = bk; C = k; }
    else                      { B = Wv; bias = bv; C = v; }
    sgemm_body(A, B, bias, C, S_LEN, D_MODEL, D_MODEL,
               blockIdx.y * 128, blockIdx.x * 128);
}

// ---------------------------------------------------------------------------
// Flash attention, fp32 (exact path, unchanged from R4).
// grid = (S/64 q-tiles, H heads), 256 threads. Register-prefetch pipelined.
// ---------------------------------------------------------------------------
#define FPI 68
#define FLASH_SMEM (4 * 64 * FPI * 4)

__global__ __launch_bounds__(256) void flash_kernel(
    const float* __restrict__ q, const float* __restrict__ k,
    const float* __restrict__ v, float* __restrict__ o_out) {
    extern __shared__ float sm[];
    float* Qs = sm;                 // [dh][r]
    float* Ks = Qs + 64 * FPI;      // [dh][c]
    float* Vs = Ks + 64 * FPI;      // [c][dh]
    float* Ps = Vs + 64 * FPI;      // [c][r]

    int head = blockIdx.y;
    int qt = blockIdx.x;
    int tid = threadIdx.x;
    int ty = tid >> 4;   // 0..15 -> rows ty*4..+3
    int tx = tid & 15;   // 0..15 -> cols tx*4..+3

    int lr[4], lc[4];
#pragma unroll
    for (int n = 0; n < 4; n++) {
        int f = tid + n * 256;
        lr[n] = f >> 4;
        lc[n] = (f & 15) * 4;
    }

    const float* qb = q + (size_t)qt * 64 * D_MODEL + head * DHD;
#pragma unroll
    for (int n = 0; n < 4; n++) {
        float4 a = *(const float4*)&qb[(size_t)lr[n] * D_MODEL + lc[n]];
        Qs[(lc[n] + 0) * FPI + lr[n]] = a.x;
        Qs[(lc[n] + 1) * FPI + lr[n]] = a.y;
        Qs[(lc[n] + 2) * FPI + lr[n]] = a.z;
        Qs[(lc[n] + 3) * FPI + lr[n]] = a.w;
    }

    float m[4], l[4], o[4][4];
#pragma unroll
    for (int i = 0; i < 4; i++) {
        m[i] = -INFINITY;
        l[i] = 0.f;
#pragma unroll
        for (int j = 0; j < 4; j++) o[i][j] = 0.f;
    }

    const float* kbase = k + head * DHD;
    const float* vbase = v + head * DHD;

    float4 kreg[4], vreg[4];
#pragma unroll
    for (int n = 0; n < 4; n++) {
        kreg[n] = *(const float4*)&kbase[(size_t)lr[n] * D_MODEL + lc[n]];
        vreg[n] = *(const float4*)&vbase[(size_t)lr[n] * D_MODEL + lc[n]];
    }

    for (int kt = 0; kt < S_LEN / 64; kt++) {
#pragma unroll
        for (int n = 0; n < 4; n++) {
            Ks[(lc[n] + 0) * FPI + lr[n]] = kreg[n].x;
            Ks[(lc[n] + 1) * FPI + lr[n]] = kreg[n].y;
            Ks[(lc[n] + 2) * FPI + lr[n]] = kreg[n].z;
            Ks[(lc[n] + 3) * FPI + lr[n]] = kreg[n].w;
            *(float4*)&Vs[lr[n] * FPI + lc[n]] = vreg[n];
        }
        __syncthreads();

        if (kt + 1 < S_LEN / 64) {
            const float* kb = kbase + (size_t)(kt + 1) * 64 * D_MODEL;
            const float* vb = vbase + (size_t)(kt + 1) * 64 * D_MODEL;
#pragma unroll
            for (int n = 0; n < 4; n++) {
                kreg[n] = *(const float4*)&kb[(size_t)lr[n] * D_MODEL + lc[n]];
                vreg[n] = *(const float4*)&vb[(size_t)lr[n] * D_MODEL + lc[n]];
            }
        }

        // S = Q K^T
        float s[4][4];
#pragma unroll
        for (int i = 0; i < 4; i++)
#pragma unroll
            for (int j = 0; j < 4; j++) s[i][j] = 0.f;

#pragma unroll 8
        for (int dh = 0; dh < 64; dh++) {
            float4 qv = *(float4*)&Qs[dh * FPI + ty * 4];
            float4 kv = *(float4*)&Ks[dh * FPI + tx * 4];
            float qa[4] = {qv.x, qv.y, qv.z, qv.w};
            float ka[4] = {kv.x, kv.y, kv.z, kv.w};
#pragma unroll
            for (int i = 0; i < 4; i++)
#pragma unroll
                for (int j = 0; j < 4; j++) s[i][j] = fmaf(qa[i], ka[j], s[i][j]);
        }

        // online softmax per row
#pragma unroll
        for (int i = 0; i < 4; i++) {
#pragma unroll
            for (int j = 0; j < 4; j++) s[i][j] *= 0.125f;  // 1/sqrt(64)
            float mx = fmaxf(fmaxf(s[i][0], s[i][1]), fmaxf(s[i][2], s[i][3]));
#pragma unroll
            for (int off = 8; off >= 1; off >>= 1)
                mx = fmaxf(mx, __shfl_xor_sync(0xffffffffu, mx, off));
            float mnew = fmaxf(m[i], mx);
            float corr = expf(m[i] - mnew);
            float rs = 0.f;
#pragma unroll
            for (int j = 0; j < 4; j++) {
                s[i][j] = expf(s[i][j] - mnew);
                rs += s[i][j];
            }
#pragma unroll
            for (int off = 8; off >= 1; off >>= 1)
                rs += __shfl_xor_sync(0xffffffffu, rs, off);
            l[i] = l[i] * corr + rs;
#pragma unroll
            for (int j = 0; j < 4; j++) o[i][j] *= corr;
            m[i] = mnew;
#pragma unroll
            for (int j = 0; j < 4; j++)
                Ps[(tx * 4 + j) * FPI + ty * 4 + i] = s[i][j];
        }
        __syncthreads();

        // O += P V
#pragma unroll 8
        for (int c = 0; c < 64; c++) {
            float4 pv = *(float4*)&Ps[c * FPI + ty * 4];
            float4 vv = *(float4*)&Vs[c * FPI + tx * 4];
            float pa[4] = {pv.x, pv.y, pv.z, pv.w};
            float va[4] = {vv.x, vv.y, vv.z, vv.w};
#pragma unroll
            for (int i = 0; i < 4; i++)
#pragma unroll
                for (int j = 0; j < 4; j++) o[i][j] = fmaf(pa[i], va[j], o[i][j]);
        }
        __syncthreads();
    }

    float* ob = o_out + (size_t)qt * 64 * D_MODEL + head * DHD;
#pragma unroll
    for (int i = 0; i < 4; i++) {
        float inv = 1.0f / l[i];
        float4 r;
        r.x = o[i][0] * inv;
        r.y = o[i][1] * inv;
        r.z = o[i][2] * inv;
        r.w = o[i][3] * inv;
        *(float4*)&ob[(size_t)(ty * 4 + i) * D_MODEL + tx * 4] = r;
    }
}

// ---------------------------------------------------------------------------
// y = LN(h + proj) * gamma + beta   (one block per row)
// ---------------------------------------------------------------------------
__global__ __launch_bounds__(256) void ln_kernel(
    const float* __restrict__ h, const float* __restrict__ p,
    const float* __restrict__ gamma, const float* __restrict__ beta,
    float* __restrict__ out) {
    int row = blockIdx.x;
    int tid = threadIdx.x;
    float v[4];
    float s = 0.f, s2 = 0.f;
#pragma unroll
    for (int n = 0; n < 4; n++) {
        int c = tid + n * 256;
        float val = h[(size_t)row * D_MODEL + c] + p[(size_t)row * D_MODEL + c];
        v[n] = val;
        s += val;
        s2 += val * val;
    }
#pragma unroll
    for (int off = 16; off >= 1; off >>= 1) {
        s += __shfl_xor_sync(0xffffffffu, s, off);
        s2 += __shfl_xor_sync(0xffffffffu, s2, off);
    }
    __shared__ float sb[8], sb2[8];
    int w = tid >> 5, lane = tid & 31;
    if (lane == 0) { sb[w] = s; sb2[w] = s2; }
    __syncthreads();
    if (tid == 0) {
        float a = 0.f, b = 0.f;
        for (int i = 0; i < 8; i++) { a += sb[i]; b += sb2[i]; }
        sb[0] = a; sb2[0] = b;
    }
    __syncthreads();
    float mean = sb[0] * (1.0f / 1024.0f);
    float var = sb2[0] * (1.0f / 1024.0f) - mean * mean;
    float inv = rsqrtf(var + 1e-5f);
#pragma unroll
    for (int n = 0; n < 4; n++) {
        int c = tid + n * 256;
        out[(size_t)row * D_MODEL + c] = (v[n] - mean) * inv * gamma[c] + beta[c];
    }
}

// ---------------------------------------------------------------------------
extern "C" void kernel_launch(void* const* d_in, const int* in_sizes, int n_in,
                              void* d_out, int out_size) {
    const float* x  = (const float*)d_in[0];
    const float* Wq = (const float*)d_in[1];
    const float* bq = (const float*)d_in[2];
    const float* Wk = (const float*)d_in[3];
    const float* bk = (const float*)d_in[4];
    const float* Wv = (const float*)d_in[5];
    const float* bv = (const float*)d_in[6];
    const float* Wo = (const float*)d_in[7];
    const float* bo = (const float*)d_in[8];
    const float* gamma = (const float*)d_in[9];
    const float* beta  = (const float*)d_in[10];
    float* out = (float*)d_out;

    void *ph, *pq, *pk, *pv, *pa, *pp;
    cudaGetSymbolAddress(&ph, g_h);
    cudaGetSymbolAddress(&pq, g_q);
    cudaGetSymbolAddress(&pk, g_k);
    cudaGetSymbolAddress(&pv, g_v);
    cudaGetSymbolAddress(&pa, g_att);
    cudaGetSymbolAddress(&pp, g_proj);

    add_pe_kernel<<<S_LEN, 256>>>(x, (float*)ph);

    dim3 qkvgrid(D_MODEL / 128, S_LEN / 128, 3);
    sgemm_qkv_kernel<<<qkvgrid, 256>>>((const float*)ph,
                                       Wq, bq, (float*)pq,
                                       Wk, bk, (float*)pk,
                                       Wv, bv, (float*)pv);

    cudaFuncSetAttribute(flash_kernel, cudaFuncAttributeMaxDynamicSharedMemorySize,
                         FLASH_SMEM);
    flash_kernel<<<dim3(S_LEN / 64, NH), 256, FLASH_SMEM>>>(
        (const float*)pq, (const float*)pk, (const float*)pv, (float*)pa);

    dim3 ggrid(D_MODEL / 128, S_LEN / 128);
    sgemm_bias_kernel<<<ggrid, 256>>>((const float*)pa, Wo, bo, (float*)pp,
                                      S_LEN, D_MODEL, D_MODEL);

    ln_kernel<<<S_LEN, 256>>>((const float*)ph, (const float*)pp, gamma, beta, out);
}

// round 8
// speedup vs baseline: 2.3605x; 2.3605x over previous
#include <cuda_runtime.h>
#include <math.h>

#define S_LEN 4096
#define D_MODEL 1024
#define NH 16
#define DHD 64

// ---- scratch (static device globals: allocation-free contract) ----
__device__ float g_h[S_LEN * D_MODEL];
__device__ float g_q[S_LEN * D_MODEL];
__device__ float g_k[S_LEN * D_MODEL];
__device__ float g_v[S_LEN * D_MODEL];
__device__ float g_att[S_LEN * D_MODEL];
__device__ float g_proj[S_LEN * D_MODEL];

// ---------------------------------------------------------------------------
// h = x + positional_encoding
// ---------------------------------------------------------------------------
__global__ void add_pe_kernel(const float* __restrict__ x, float* __restrict__ h) {
    int srow = blockIdx.x;
    int tid = threadIdx.x;
#pragma unroll
    for (int n = 0; n < 4; n++) {
        int d = tid + n * 256;
        float arg = (float)(d & ~1) * (-9.2103403719761836f / 1024.0f);  // -ln(10000)/D
        float dv = expf(arg);
        float a = (float)srow * dv;
        float pe = (d & 1) ? cosf(a) : sinf(a);
        int idx = srow * D_MODEL + d;
        h[idx] = x[idx] + pe;
    }
}

// ---------------------------------------------------------------------------
// tf32 helpers
// ---------------------------------------------------------------------------
__device__ __forceinline__ unsigned f2tf32(float x) {
    unsigned r;
    asm("cvt.rna.tf32.f32 %0, %1;" : "=r"(r) : "f"(x));
    return r;
}

__device__ __forceinline__ void mma_tf32(
    float& c0, float& c1, float& c2, float& c3,
    unsigned a0, unsigned a1, unsigned a2, unsigned a3,
    unsigned b0, unsigned b1) {
    asm("mma.sync.aligned.m16n8k8.row.col.f32.tf32.tf32.f32 "
        "{%0,%1,%2,%3}, {%4,%5,%6,%7}, {%8,%9}, {%0,%1,%2,%3};"
        : "+f"(c0), "+f"(c1), "+f"(c2), "+f"(c3)
        : "r"(a0), "r"(a1), "r"(a2), "r"(a3), "r"(b0), "r"(b1));
}

// ---------------------------------------------------------------------------
// 128x128x16 tf32 tensor-core GEMM body (validated R6), double-buffered.
// ---------------------------------------------------------------------------
#define KT 16
#define PITCH 136

__device__ __forceinline__ void sgemm_body(
    const float* __restrict__ A, const float* __restrict__ B,
    const float* __restrict__ bias, float* __restrict__ C,
    int M, int N, int K, int m0, int n0) {
    __shared__ unsigned As[2][KT][PITCH];
    __shared__ unsigned Bs[2][KT][PITCH];

    int tid = threadIdx.x;
    int wid = tid >> 5;
    int lane = tid & 31;
    int gid = lane >> 2;       // 0..7
    int tig = lane & 3;        // 0..3
    int wm = (wid & 3) * 32;   // warp row offset in tile
    int wn = (wid >> 2) * 64;  // warp col offset in tile

    int arow = tid >> 1;
    int acol = (tid & 1) * 4;
    int brow = tid >> 5;
    int bcol = (tid & 31) * 4;

    const float* Aptr = &A[(size_t)(m0 + arow) * K + acol];
    const float* Bptr = &B[(size_t)brow * N + n0 + bcol];

    float acc[2][8][4];
#pragma unroll
    for (int mt = 0; mt < 2; mt++)
#pragma unroll
        for (int nt = 0; nt < 8; nt++)
#pragma unroll
            for (int r = 0; r < 4; r++) acc[mt][nt][r] = 0.f;

    float4 a0p = *(const float4*)Aptr;
    float4 a1p = *(const float4*)(Aptr + 8);
    float4 b0p = *(const float4*)Bptr;
    float4 b1p = *(const float4*)(Bptr + (size_t)8 * N);
#pragma unroll
    for (int i = 0; i < 4; i++) {
        As[0][acol + i][arow]     = f2tf32(((const float*)&a0p)[i]);
        As[0][acol + 8 + i][arow] = f2tf32(((const float*)&a1p)[i]);
        Bs[0][brow][bcol + i]     = f2tf32(((const float*)&b0p)[i]);
        Bs[0][brow + 8][bcol + i] = f2tf32(((const float*)&b1p)[i]);
    }
    __syncthreads();

    int buf = 0;
    for (int k0 = 0; k0 < K; k0 += KT) {
        if (k0 + KT < K) {
            a0p = *(const float4*)(Aptr + k0 + KT);
            a1p = *(const float4*)(Aptr + k0 + KT + 8);
            b0p = *(const float4*)(Bptr + (size_t)(k0 + KT) * N);
            b1p = *(const float4*)(Bptr + (size_t)(k0 + KT + 8) * N);
        }

#pragma unroll
        for (int ks = 0; ks < KT; ks += 8) {
            unsigned af[2][4], bf[8][2];
#pragma unroll
            for (int mt = 0; mt < 2; mt++) {
                int r = wm + mt * 16 + gid;
                af[mt][0] = As[buf][ks + tig][r];
                af[mt][1] = As[buf][ks + tig][r + 8];
                af[mt][2] = As[buf][ks + tig + 4][r];
                af[mt][3] = As[buf][ks + tig + 4][r + 8];
            }
#pragma unroll
            for (int nt = 0; nt < 8; nt++) {
                int c = wn + nt * 8 + gid;
                bf[nt][0] = Bs[buf][ks + tig][c];
                bf[nt][1] = Bs[buf][ks + tig + 4][c];
            }
#pragma unroll
            for (int mt = 0; mt < 2; mt++)
#pragma unroll
                for (int nt = 0; nt < 8; nt++)
                    mma_tf32(acc[mt][nt][0], acc[mt][nt][1],
                             acc[mt][nt][2], acc[mt][nt][3],
                             af[mt][0], af[mt][1], af[mt][2], af[mt][3],
                             bf[nt][0], bf[nt][1]);
        }

        if (k0 + KT < K) {
            int nb = buf ^ 1;
#pragma unroll
            for (int i = 0; i < 4; i++) {
                As[nb][acol + i][arow]     = f2tf32(((const float*)&a0p)[i]);
                As[nb][acol + 8 + i][arow] = f2tf32(((const float*)&a1p)[i]);
                Bs[nb][brow][bcol + i]     = f2tf32(((const float*)&b0p)[i]);
                Bs[nb][brow + 8][bcol + i] = f2tf32(((const float*)&b1p)[i]);
            }
            __syncthreads();
            buf = nb;
        }
    }

#pragma unroll
    for (int mt = 0; mt < 2; mt++) {
#pragma unroll
        for (int nt = 0; nt < 8; nt++) {
            int row = m0 + wm + mt * 16 + gid;
            int col = n0 + wn + nt * 8 + tig * 2;
            float2 r0, r1;
            r0.x = acc[mt][nt][0] + bias[col];
            r0.y = acc[mt][nt][1] + bias[col + 1];
            r1.x = acc[mt][nt][2] + bias[col];
            r1.y = acc[mt][nt][3] + bias[col + 1];
            *(float2*)&C[(size_t)row * N + col]       = r0;
            *(float2*)&C[(size_t)(row + 8) * N + col] = r1;
        }
    }
}

__global__ __launch_bounds__(256) void sgemm_bias_kernel(
    const float* __restrict__ A, const float* __restrict__ B,
    const float* __restrict__ bias, float* __restrict__ C,
    int M, int N, int K) {
    sgemm_body(A, B, bias, C, M, N, K, blockIdx.y * 128, blockIdx.x * 128);
}

__global__ __launch_bounds__(256) void sgemm_qkv_kernel(
    const float* __restrict__ A,
    const float* __restrict__ Wq, const float* __restrict__ bq, float* __restrict__ q,
    const float* __restrict__ Wk, const float* __restrict__ bk, float* __restrict__ k,
    const float* __restrict__ Wv, const float* __restrict__ bv, float* __restrict__ v) {
    const float* B;
    const float* bias;
    float* C;
    if (blockIdx.z == 0)      { B = Wq; bias = bq; C = q; }
    else if (blockIdx.z == 1) { B = Wk; bias = bk; C = k; }
    else                      { B = Wv; bias = bv; C = v; }
    sgemm_body(A, B, bias, C, S_LEN, D_MODEL, D_MODEL,
               blockIdx.y * 128, blockIdx.x * 128);
}

// ---------------------------------------------------------------------------
// Flash attention with tf32 tensor cores.
// grid = (S/64 q-tiles, H heads), 128 threads (4 warps).
// Warp w owns q-rows [w*16, w*16+16). Q A-fragments preloaded in registers
// (scaled by 1/8 pre-conversion, exact). K[key][dh] and V[key][dh] in natural
// row-major smem are directly the col-major B operands for QK^T and PV.
// P round-trips through smem (C-frag -> A-frag reshape), warp-private rows.
// Smem pitch 68 words: QK^T B-loads conflict-free; PV loads worst-case 2-way.
// ---------------------------------------------------------------------------
#define FP 68
#define FLASH_SMEM (3 * 64 * FP * 4)

__global__ __launch_bounds__(128, 4) void flash_tc_kernel(
    const float* __restrict__ q, const float* __restrict__ k,
    const float* __restrict__ v, float* __restrict__ o_out) {
    extern __shared__ unsigned fsm[];
    unsigned* Ks = fsm;               // [key][dh]  64 x FP
    unsigned* Vs = fsm + 64 * FP;     // [key][dh]
    unsigned* Ps = fsm + 2 * 64 * FP; // [qrow][key]

    int head = blockIdx.y;
    int qt = blockIdx.x;
    int tid = threadIdx.x;
    int wid = tid >> 5;
    int lane = tid & 31;
    int gid = lane >> 2;  // 0..7
    int tig = lane & 3;   // 0..3

    // preload Q A-fragments (x 1/8 scale), constant over all kt tiles
    unsigned aq[8][4];
    {
        const float* qb = q + (size_t)(qt * 64 + wid * 16) * D_MODEL + head * DHD;
#pragma unroll
        for (int ks = 0; ks < 8; ks++) {
            int c0 = ks * 8 + tig;
            aq[ks][0] = f2tf32(0.125f * qb[(size_t)gid * D_MODEL + c0]);
            aq[ks][1] = f2tf32(0.125f * qb[(size_t)(gid + 8) * D_MODEL + c0]);
            aq[ks][2] = f2tf32(0.125f * qb[(size_t)gid * D_MODEL + c0 + 4]);
            aq[ks][3] = f2tf32(0.125f * qb[(size_t)(gid + 8) * D_MODEL + c0 + 4]);
        }
    }

    float m0 = -INFINITY, m1 = -INFINITY, l0 = 0.f, l1 = 0.f;
    float o[8][4];
#pragma unroll
    for (int nt = 0; nt < 8; nt++)
#pragma unroll
        for (int r = 0; r < 4; r++) o[nt][r] = 0.f;

    int pr0 = wid * 16 + gid;       // this thread's P/O rows (warp-local tile)
    int pr1 = pr0 + 8;

    for (int kt = 0; kt < S_LEN / 64; kt++) {
        // ---- load K,V tile -> smem (tf32) ----
        const float* kb = k + (size_t)kt * 64 * D_MODEL + head * DHD;
        const float* vb = v + (size_t)kt * 64 * D_MODEL + head * DHD;
#pragma unroll
        for (int n = 0; n < 8; n++) {
            int f4 = n * 128 + tid;
            int key = f4 >> 4;
            int d4 = (f4 & 15) * 4;
            float4 kv4 = *(const float4*)&kb[(size_t)key * D_MODEL + d4];
            float4 vv4 = *(const float4*)&vb[(size_t)key * D_MODEL + d4];
            uint4 ku = {f2tf32(kv4.x), f2tf32(kv4.y), f2tf32(kv4.z), f2tf32(kv4.w)};
            uint4 vu = {f2tf32(vv4.x), f2tf32(vv4.y), f2tf32(vv4.z), f2tf32(vv4.w)};
            *(uint4*)&Ks[key * FP + d4] = ku;
            *(uint4*)&Vs[key * FP + d4] = vu;
        }
        __syncthreads();

        // ---- S = (Q/8) K^T  (pre-scaled) ----
        float s[8][4];
#pragma unroll
        for (int nt = 0; nt < 8; nt++)
#pragma unroll
            for (int r = 0; r < 4; r++) s[nt][r] = 0.f;

#pragma unroll
        for (int ks = 0; ks < 8; ks++) {
#pragma unroll
            for (int nt = 0; nt < 8; nt++) {
                int key = nt * 8 + gid;
                unsigned b0 = Ks[key * FP + ks * 8 + tig];
                unsigned b1 = Ks[key * FP + ks * 8 + tig + 4];
                mma_tf32(s[nt][0], s[nt][1], s[nt][2], s[nt][3],
                         aq[ks][0], aq[ks][1], aq[ks][2], aq[ks][3], b0, b1);
            }
        }

        // ---- online softmax (rows pr0=gid, pr1=gid+8 within warp tile) ----
        float mx0 = -INFINITY, mx1 = -INFINITY;
#pragma unroll
        for (int nt = 0; nt < 8; nt++) {
            mx0 = fmaxf(mx0, fmaxf(s[nt][0], s[nt][1]));
            mx1 = fmaxf(mx1, fmaxf(s[nt][2], s[nt][3]));
        }
        mx0 = fmaxf(mx0, __shfl_xor_sync(0xffffffffu, mx0, 1));
        mx0 = fmaxf(mx0, __shfl_xor_sync(0xffffffffu, mx0, 2));
        mx1 = fmaxf(mx1, __shfl_xor_sync(0xffffffffu, mx1, 1));
        mx1 = fmaxf(mx1, __shfl_xor_sync(0xffffffffu, mx1, 2));

        float mn0 = fmaxf(m0, mx0);
        float mn1 = fmaxf(m1, mx1);
        float c0 = __expf(m0 - mn0);
        float c1 = __expf(m1 - mn1);
        float rs0 = 0.f, rs1 = 0.f;
#pragma unroll
        for (int nt = 0; nt < 8; nt++) {
            s[nt][0] = __expf(s[nt][0] - mn0);
            s[nt][1] = __expf(s[nt][1] - mn0);
            s[nt][2] = __expf(s[nt][2] - mn1);
            s[nt][3] = __expf(s[nt][3] - mn1);
            rs0 += s[nt][0] + s[nt][1];
            rs1 += s[nt][2] + s[nt][3];
        }
        rs0 += __shfl_xor_sync(0xffffffffu, rs0, 1);
        rs0 += __shfl_xor_sync(0xffffffffu, rs0, 2);
        rs1 += __shfl_xor_sync(0xffffffffu, rs1, 1);
        rs1 += __shfl_xor_sync(0xffffffffu, rs1, 2);
        l0 = l0 * c0 + rs0;
        l1 = l1 * c1 + rs1;
        m0 = mn0;
        m1 = mn1;
#pragma unroll
        for (int nt = 0; nt < 8; nt++) {
            o[nt][0] *= c0;
            o[nt][1] *= c0;
            o[nt][2] *= c1;
            o[nt][3] *= c1;
        }

        // ---- P -> smem (tf32), warp-private rows ----
#pragma unroll
        for (int nt = 0; nt < 8; nt++) {
            int col = nt * 8 + tig * 2;
            uint2 p0 = {f2tf32(s[nt][0]), f2tf32(s[nt][1])};
            uint2 p1 = {f2tf32(s[nt][2]), f2tf32(s[nt][3])};
            *(uint2*)&Ps[pr0 * FP + col] = p0;
            *(uint2*)&Ps[pr1 * FP + col] = p1;
        }
        __syncwarp();

        // ---- O += P V ----
#pragma unroll
        for (int ks = 0; ks < 8; ks++) {
            unsigned ap0 = Ps[pr0 * FP + ks * 8 + tig];
            unsigned ap1 = Ps[pr1 * FP + ks * 8 + tig];
            unsigned ap2 = Ps[pr0 * FP + ks * 8 + tig + 4];
            unsigned ap3 = Ps[pr1 * FP + ks * 8 + tig + 4];
#pragma unroll
            for (int nt = 0; nt < 8; nt++) {
                unsigned b0 = Vs[(ks * 8 + tig) * FP + nt * 8 + gid];
                unsigned b1 = Vs[(ks * 8 + tig + 4) * FP + nt * 8 + gid];
                mma_tf32(o[nt][0], o[nt][1], o[nt][2], o[nt][3],
                         ap0, ap1, ap2, ap3, b0, b1);
            }
        }
        __syncthreads();  // Ks/Vs reused next tile
    }

    // ---- epilogue: O / l ----
    float inv0 = 1.0f / l0;
    float inv1 = 1.0f / l1;
    float* ob = o_out + (size_t)(qt * 64 + wid * 16) * D_MODEL + head * DHD;
#pragma unroll
    for (int nt = 0; nt < 8; nt++) {
        int col = nt * 8 + tig * 2;
        float2 r0 = {o[nt][0] * inv0, o[nt][1] * inv0};
        float2 r1 = {o[nt][2] * inv1, o[nt][3] * inv1};
        *(float2*)&ob[(size_t)gid * D_MODEL + col]       = r0;
        *(float2*)&ob[(size_t)(gid + 8) * D_MODEL + col] = r1;
    }
}

// ---------------------------------------------------------------------------
// y = LN(h + proj) * gamma + beta   (one block per row)
// ---------------------------------------------------------------------------
__global__ __launch_bounds__(256) void ln_kernel(
    const float* __restrict__ h, const float* __restrict__ p,
    const float* __restrict__ gamma, const float* __restrict__ beta,
    float* __restrict__ out) {
    int row = blockIdx.x;
    int tid = threadIdx.x;
    float v[4];
    float s = 0.f, s2 = 0.f;
#pragma unroll
    for (int n = 0; n < 4; n++) {
        int c = tid + n * 256;
        float val = h[(size_t)row * D_MODEL + c] + p[(size_t)row * D_MODEL + c];
        v[n] = val;
        s += val;
        s2 += val * val;
    }
#pragma unroll
    for (int off = 16; off >= 1; off >>= 1) {
        s += __shfl_xor_sync(0xffffffffu, s, off);
        s2 += __shfl_xor_sync(0xffffffffu, s2, off);
    }
    __shared__ float sb[8], sb2[8];
    int w = tid >> 5, lane = tid & 31;
    if (lane == 0) { sb[w] = s; sb2[w] = s2; }
    __syncthreads();
    if (tid == 0) {
        float a = 0.f, b = 0.f;
        for (int i = 0; i < 8; i++) { a += sb[i]; b += sb2[i]; }
        sb[0] = a; sb2[0] = b;
    }
    __syncthreads();
    float mean = sb[0] * (1.0f / 1024.0f);
    float var = sb2[0] * (1.0f / 1024.0f) - mean * mean;
    float inv = rsqrtf(var + 1e-5f);
#pragma unroll
    for (int n = 0; n < 4; n++) {
        int c = tid + n * 256;
        out[(size_t)row * D_MODEL + c] = (v[n] - mean) * inv * gamma[c] + beta[c];
    }
}

// ---------------------------------------------------------------------------
extern "C" void kernel_launch(void* const* d_in, const int* in_sizes, int n_in,
                              void* d_out, int out_size) {
    const float* x  = (const float*)d_in[0];
    const float* Wq = (const float*)d_in[1];
    const float* bq = (const float*)d_in[2];
    const float* Wk = (const float*)d_in[3];
    const float* bk = (const float*)d_in[4];
    const float* Wv = (const float*)d_in[5];
    const float* bv = (const float*)d_in[6];
    const float* Wo = (const float*)d_in[7];
    const float* bo = (const float*)d_in[8];
    const float* gamma = (const float*)d_in[9];
    const float* beta  = (const float*)d_in[10];
    float* out = (float*)d_out;

    void *ph, *pq, *pk, *pv, *pa, *pp;
    cudaGetSymbolAddress(&ph, g_h);
    cudaGetSymbolAddress(&pq, g_q);
    cudaGetSymbolAddress(&pk, g_k);
    cudaGetSymbolAddress(&pv, g_v);
    cudaGetSymbolAddress(&pa, g_att);
    cudaGetSymbolAddress(&pp, g_proj);

    add_pe_kernel<<<S_LEN, 256>>>(x, (float*)ph);

    dim3 qkvgrid(D_MODEL / 128, S_LEN / 128, 3);
    sgemm_qkv_kernel<<<qkvgrid, 256>>>((const float*)ph,
                                       Wq, bq, (float*)pq,
                                       Wk, bk, (float*)pk,
                                       Wv, bv, (float*)pv);

    cudaFuncSetAttribute(flash_tc_kernel, cudaFuncAttributeMaxDynamicSharedMemorySize,
                         FLASH_SMEM);
    flash_tc_kernel<<<dim3(S_LEN / 64, NH), 128, FLASH_SMEM>>>(
        (const float*)pq, (const float*)pk, (const float*)pv, (float*)pa);

    dim3 ggrid(D_MODEL / 128, S_LEN / 128);
    sgemm_bias_kernel<<<ggrid, 256>>>((const float*)pa, Wo, bo, (float*)pp,
                                      S_LEN, D_MODEL, D_MODEL);

    ln_kernel<<<S_LEN, 256>>>((const float*)ph, (const float*)pp, gamma, beta, out);
}